// round 12
// baseline (speedup 1.0000x reference)
#include <cuda_runtime.h>
#include <cuda_bf16.h>
#include <cstdint>

#define NN   8192
#define DIN  512
#define DOUT 256
#define KSLICES 2
#define KSL  (NN / KSLICES)     // 4096 k per slice
#define KT   64                 // k per chunk
#define NCHUNK (KSL / KT)       // 64
#define HNCH (DIN / KT)         // 8 chunks for hWT gemm

// ---------------- scratch (__device__ globals: allocation-free rule) --------
__device__ float          g_f1  [NN];
__device__ float          g_f2  [NN];
__device__ unsigned       g_fmax_u;                      // ordered-uint max(f2)
__device__ float2         g_E   [NN];                    // (exp(f2), exp(.2 f2))
__device__ float          g_wa  [2 * DIN];               // W@a1, W@a2
__device__ unsigned short g_hh  [(size_t)NN * DIN];      // h fp16
__device__ unsigned short g_Wt  [(size_t)DOUT * DIN];    // W^T fp16 [c][k]
__device__ unsigned short g_hWT [(size_t)DOUT * NN];     // hW^T fp16 [c][i]
__device__ float          g_np  [(size_t)KSLICES * NN * DOUT]; // partial numerators
__device__ float          g_zp  [KSLICES * NN];                // partial Z

// ---------------- helpers ---------------------------------------------------
__device__ __forceinline__ uint32_t smem_u32(const void* p) {
    uint32_t a;
    asm("{ .reg .u64 t; cvta.to.shared.u64 t, %1; cvt.u32.u64 %0, t; }"
        : "=r"(a) : "l"(p));
    return a;
}
__device__ __forceinline__ uint32_t sw128(uint32_t off) {
    return off ^ ((off >> 3) & 0x70);
}
// packs (lo, hi) -> low 16 = f16(lo), high 16 = f16(hi)
__device__ __forceinline__ unsigned pack_f16x2(float lo, float hi) {
    unsigned r;
    asm("cvt.rn.f16x2.f32 %0, %1, %2;" : "=r"(r) : "f"(hi), "f"(lo));
    return r;
}
__device__ __forceinline__ void cp16(uint32_t smem, const void* g) {
    asm volatile("cp.async.cg.shared.global [%0], [%1], 16;"
                 :: "r"(smem), "l"(g));
}
__device__ __forceinline__ void cp_commit() {
    asm volatile("cp.async.commit_group;");
}
__device__ __forceinline__ void cp_wait0() {
    asm volatile("cp.async.wait_group 0;" ::: "memory");
}
__device__ __forceinline__ void ldsm4(uint32_t* r, uint32_t addr) {
    asm volatile("ldmatrix.sync.aligned.m8n8.x4.shared.b16 {%0,%1,%2,%3}, [%4];"
                 : "=r"(r[0]), "=r"(r[1]), "=r"(r[2]), "=r"(r[3]) : "r"(addr));
}
__device__ __forceinline__ void mma16816(float* c, const uint32_t* a,
                                         uint32_t b0, uint32_t b1) {
    asm volatile(
        "mma.sync.aligned.m16n8k16.row.col.f32.f16.f16.f32 "
        "{%0,%1,%2,%3},{%4,%5,%6,%7},{%8,%9},{%0,%1,%2,%3};"
        : "+f"(c[0]), "+f"(c[1]), "+f"(c[2]), "+f"(c[3])
        : "r"(a[0]), "r"(a[1]), "r"(a[2]), "r"(a[3]), "r"(b0), "r"(b1));
}
// ordered-uint encoding for float atomicMax (monotone for all floats)
__device__ __forceinline__ unsigned f2ord(float x) {
    unsigned b = __float_as_uint(x);
    return (b & 0x80000000u) ? ~b : (b | 0x80000000u);
}
__device__ __forceinline__ float ord2f(unsigned u) {
    unsigned b = (u & 0x80000000u) ? (u & 0x7fffffffu) : ~u;
    return __uint_as_float(b);
}

// SMEM map shared by k_hwt / k_gat: [0..2KB) scratch; 2 stages of A 8K | B 32K
#define ZOFF        0
#define TILE0       2048
#define STAGE_BYTES 40960
#define SMEM_TOTAL  (TILE0 + 2 * STAGE_BYTES)

// ---------------------------------------------------------------------------
// k_conv_h: h fp32 -> g_hh fp16
// ---------------------------------------------------------------------------
__global__ void k_conv_h(const float* __restrict__ h)
{
    const size_t i = ((size_t)blockIdx.x * 256 + threadIdx.x) * 8;
    float4 a = *(const float4*)(h + i);
    float4 b = *(const float4*)(h + i + 4);
    uint4 o;
    o.x = pack_f16x2(a.x, a.y);
    o.y = pack_f16x2(a.z, a.w);
    o.z = pack_f16x2(b.x, b.y);
    o.w = pack_f16x2(b.z, b.w);
    *(uint4*)(g_hh + i) = o;
}

// ---------------------------------------------------------------------------
// k_prep_w: g_wa[k] = sum_c W[k][c]*a1[c] (and a2); g_Wt[c][k] = fp16 W[k][c];
// also resets g_fmax_u (deterministic across graph replays).
// ---------------------------------------------------------------------------
__global__ void k_prep_w(const float* __restrict__ W, const float* __restrict__ a)
{
    const int tid  = threadIdx.x;
    const int lane = tid & 31;
    const int wid  = tid >> 5;       // 0..15

    if (tid == 0) g_fmax_u = 0u;     // ordered-uint of -inf

    for (int k = wid; k < DIN; k += 16) {
        float s1 = 0.f, s2 = 0.f;
        #pragma unroll
        for (int c = lane; c < DOUT; c += 32) {
            float w = W[k * DOUT + c];
            s1 = fmaf(w, a[c], s1);
            s2 = fmaf(w, a[DOUT + c], s2);
        }
        #pragma unroll
        for (int o = 16; o; o >>= 1) {
            s1 += __shfl_xor_sync(~0u, s1, o);
            s2 += __shfl_xor_sync(~0u, s2, o);
        }
        if (lane == 0) { g_wa[k] = s1; g_wa[DIN + k] = s2; }
    }

    for (int idx = tid; idx < DIN * DOUT; idx += 512) {
        const int k = idx >> 8;          // DOUT = 256
        const int c = idx & 255;
        g_Wt[(size_t)c * DIN + k] = (unsigned short)(pack_f16x2(W[idx], 0.f) & 0xffff);
    }
}

// ---------------------------------------------------------------------------
// k_f1f2h: f1 = h @ wa1, f2 = h @ wa2  (warp per row) + atomicMax of f2
// ---------------------------------------------------------------------------
__global__ void k_f1f2h(const float* __restrict__ h)
{
    const int row  = blockIdx.x * 8 + threadIdx.y;
    const int lane = threadIdx.x;
    const float* hr = h + (size_t)row * DIN;

    float s1 = 0.f, s2 = 0.f;
    #pragma unroll
    for (int k = lane; k < DIN; k += 32) {
        float v = hr[k];
        s1 = fmaf(v, g_wa[k], s1);
        s2 = fmaf(v, g_wa[DIN + k], s2);
    }
    #pragma unroll
    for (int o = 16; o; o >>= 1) {
        s1 += __shfl_xor_sync(~0u, s1, o);
        s2 += __shfl_xor_sync(~0u, s2, o);
    }
    if (lane == 0) {
        g_f1[row] = s1;
        g_f2[row] = s2;
        atomicMax(&g_fmax_u, f2ord(s2));
    }
}

// ---------------------------------------------------------------------------
// k_E: g_E[j] = (exp(f2_j), exp(0.2 f2_j))
// ---------------------------------------------------------------------------
__global__ void k_E()
{
    const int i = blockIdx.x * 1024 + threadIdx.x;
    float f2 = g_f2[i];
    g_E[i] = make_float2(__expf(f2), __expf(0.2f * f2));
}

// ---------------------------------------------------------------------------
// k_hwt: g_hWT[c][i] = fp16( h @ W )^T via fp16 tensor MMA.
// 64(i) x 256(c) tile, 256 thr, 8 warps 2m x 4n, K=512 in 8 chunks.
// ---------------------------------------------------------------------------
__global__ __launch_bounds__(256, 2) void k_hwt()
{
    extern __shared__ __align__(1024) char smem[];
    const uint32_t sb = smem_u32(smem);
    const int tid  = threadIdx.x;
    const int lane = tid & 31;
    const int wid  = tid >> 5;
    const int wm   = wid & 1;
    const int wn   = wid >> 1;
    const int i0   = blockIdx.x * 64;

    int AOFF[2], BOFF[2];
    #pragma unroll
    for (int s = 0; s < 2; s++) {
        AOFF[s] = TILE0 + s * STAGE_BYTES;
        BOFF[s] = AOFF[s] + 8192;
    }

    const int arow = tid >> 2, aseg = tid & 3;   // A loader
    const int rB = tid;                          // B loader (row c)

    auto load_stage = [&](int jt, int s) {
        const size_t ga = (size_t)(i0 + arow) * DIN + jt * KT + aseg * 16;
        cp16(sb + AOFF[s] + sw128((uint32_t)(arow * 128 + aseg * 32)),      g_hh + ga);
        cp16(sb + AOFF[s] + sw128((uint32_t)(arow * 128 + aseg * 32 + 16)), g_hh + ga + 8);
        const size_t gb = (size_t)rB * DIN + jt * KT;
        #pragma unroll
        for (int cc = 0; cc < 8; cc++)
            cp16(sb + BOFF[s] + sw128((uint32_t)(rB * 128 + cc * 16)), g_Wt + gb + cc * 8);
    };

    const int aRow = lane & 15;
    const int aH   = lane >> 4;
    const int bRow = (lane & 7) | ((lane >> 4) << 3);
    const int bH   = (lane >> 3) & 1;

    float acc[2][8][4];
    #pragma unroll
    for (int mt = 0; mt < 2; mt++)
        #pragma unroll
        for (int nt = 0; nt < 8; nt++)
            #pragma unroll
            for (int q = 0; q < 4; q++) acc[mt][nt][q] = 0.f;

    load_stage(0, 0);
    cp_commit();
    cp_wait0();
    __syncthreads();

    #pragma unroll 1
    for (int jt = 0; jt < HNCH; ++jt) {
        const int s = jt & 1;
        if (jt + 1 < HNCH) { load_stage(jt + 1, s ^ 1); cp_commit(); }

        #pragma unroll
        for (int kk = 0; kk < 4; kk++) {
            uint32_t ah[2][4];
            #pragma unroll
            for (int mt = 0; mt < 2; mt++)
                ldsm4(ah[mt], sb + AOFF[s] + sw128((uint32_t)(
                    (wm * 32 + mt * 16 + aRow) * 128 + kk * 32 + aH * 16)));
            uint32_t bh[4][4];
            #pragma unroll
            for (int p = 0; p < 4; p++)
                ldsm4(bh[p], sb + BOFF[s] + sw128((uint32_t)(
                    (wn * 64 + p * 16 + bRow) * 128 + kk * 32 + bH * 16)));
            #pragma unroll
            for (int mt = 0; mt < 2; mt++)
                #pragma unroll
                for (int p = 0; p < 4; p++) {
                    mma16816(acc[mt][2 * p],     ah[mt], bh[p][0], bh[p][1]);
                    mma16816(acc[mt][2 * p + 1], ah[mt], bh[p][2], bh[p][3]);
                }
        }

        if (jt + 1 < HNCH) cp_wait0();
        __syncthreads();
    }

    // ---- transpose epilogue: frags -> smem fp16 [i][c] (pitch 258) -> [c][i]
    #define TP 258
    unsigned short* buf = (unsigned short*)(smem + TILE0);
    {
        const int g  = lane >> 2;
        const int tg = lane & 3;
        #pragma unroll
        for (int mt = 0; mt < 2; mt++)
            #pragma unroll
            for (int nt = 0; nt < 8; nt++) {
                const int r0  = wm * 32 + mt * 16 + g;
                const int col = wn * 64 + nt * 8 + tg * 2;
                *(unsigned*)(buf + r0 * TP + col) =
                    pack_f16x2(acc[mt][nt][0], acc[mt][nt][1]);
                *(unsigned*)(buf + (r0 + 8) * TP + col) =
                    pack_f16x2(acc[mt][nt][2], acc[mt][nt][3]);
            }
    }
    __syncthreads();
    {
        uint32_t pk[32];
        #pragma unroll
        for (int q = 0; q < 32; q++) {
            unsigned lo = buf[(2 * q) * TP + tid];
            unsigned hi = buf[(2 * q + 1) * TP + tid];
            pk[q] = lo | (hi << 16);
        }
        unsigned short* dst = g_hWT + (size_t)tid * NN + i0;
        #pragma unroll
        for (int q = 0; q < 8; q++)
            *(uint4*)(dst + q * 8) =
                make_uint4(pk[4 * q], pk[4 * q + 1], pk[4 * q + 2], pk[4 * q + 3]);
    }
}

// ---------------------------------------------------------------------------
// k_gat_mma: R5 structure (M=64 x N=256, 256 thr, 2 CTA/SM, KSLICES=2,
// grid 256) + factorized no-MUFU w-gen:
//   w = adj ? max(c1_i * E1_j, c2_i * E2_j) : 0
//   c1 = exp(f1-M), c2 = exp(.2 f1-M), E1 = exp(f2), E2 = exp(.2 f2)
// ---------------------------------------------------------------------------
__global__ __launch_bounds__(256, 2) void k_gat_mma(const int* __restrict__ adj)
{
    extern __shared__ __align__(1024) char smem[];
    const uint32_t sb = smem_u32(smem);

    const int tid  = threadIdx.x;
    const int lane = tid & 31;
    const int wid  = tid >> 5;
    const int wm   = wid & 1;      // warp row  (32 rows)
    const int wn   = wid >> 1;     // warp col  (64 cols)
    const int i0   = blockIdx.x * 64;
    const int ks   = blockIdx.y;
    const int k0s  = ks * KSL;

    int AOFF[2], BOFF[2];
    #pragma unroll
    for (int s = 0; s < 2; s++) {
        AOFF[s] = TILE0 + s * STAGE_BYTES;
        BOFF[s] = AOFF[s] + 8192;
    }

    // ---- w-gen mapping: row iw, 16 k's starting at kb ----
    const int iw = tid >> 2;             // 0..63
    const int kb = (tid & 3) * 16;
    const float f1v  = g_f1[i0 + iw];
    const float fmax = ord2f(g_fmax_u);
    const float smax = f1v + fmax;
    const float Mrow = fmaxf(smax, 0.2f * smax);
    const float c1 = __expf(f1v - Mrow);
    const float c2 = __expf(0.2f * f1v - Mrow);
    float zacc = 0.f;

    const int rB = tid;                  // B loader: row = tid

    float acc[2][8][4];
    #pragma unroll
    for (int mt = 0; mt < 2; mt++)
        #pragma unroll
        for (int nt = 0; nt < 8; nt++)
            #pragma unroll
            for (int q = 0; q < 4; q++) acc[mt][nt][q] = 0.f;

    auto load_B = [&](int jt, int s) {
        const size_t gk = (size_t)rB * NN + k0s + jt * KT;
        #pragma unroll
        for (int cc = 0; cc < 8; cc++) {
            const uint32_t off = sw128((uint32_t)(rB * 128 + cc * 16));
            cp16(sb + BOFF[s] + off, g_hWT + gk + cc * 8);
        }
    };

    auto gen_A = [&](int jt, int s) {
        const int4*   ap = (const int4*)(adj + (size_t)(i0 + iw) * NN + k0s + jt * KT + kb);
        const float4* ep = (const float4*)(g_E + k0s + jt * KT + kb);   // 2 j per float4
        int4 A0 = ap[0], A1 = ap[1], A2 = ap[2], A3 = ap[3];
        const int av[16] = {A0.x,A0.y,A0.z,A0.w, A1.x,A1.y,A1.z,A1.w,
                            A2.x,A2.y,A2.z,A2.w, A3.x,A3.y,A3.z,A3.w};
        float w[16];
        #pragma unroll
        for (int m = 0; m < 8; m++) {
            float4 e = ep[m];     // (E1_j0, E2_j0, E1_j1, E2_j1)
            float w0 = fmaxf(c1 * e.x, c2 * e.y);
            float w1 = fmaxf(c1 * e.z, c2 * e.w);
            w0 = (av[2 * m]     > 0) ? w0 : 0.f;
            w1 = (av[2 * m + 1] > 0) ? w1 : 0.f;
            zacc += w0 + w1;
            w[2 * m] = w0; w[2 * m + 1] = w1;
        }
        uint4 H0, H1;
        H0.x = pack_f16x2(w[0],  w[1]);  H0.y = pack_f16x2(w[2],  w[3]);
        H0.z = pack_f16x2(w[4],  w[5]);  H0.w = pack_f16x2(w[6],  w[7]);
        H1.x = pack_f16x2(w[8],  w[9]);  H1.y = pack_f16x2(w[10], w[11]);
        H1.z = pack_f16x2(w[12], w[13]); H1.w = pack_f16x2(w[14], w[15]);
        const uint32_t o0 = sw128((uint32_t)(iw * 128 + kb * 2));
        const uint32_t o1 = sw128((uint32_t)(iw * 128 + kb * 2 + 16));
        *(uint4*)(smem + AOFF[s] + o0) = H0;
        *(uint4*)(smem + AOFF[s] + o1) = H1;
    };

    const int aRow = lane & 15;
    const int aH   = lane >> 4;
    const int bRow = (lane & 7) | ((lane >> 4) << 3);
    const int bH   = (lane >> 3) & 1;

    // ---- prologue ----
    load_B(0, 0);
    cp_commit();
    gen_A(0, 0);
    cp_wait0();
    __syncthreads();

    #pragma unroll 1
    for (int jt = 0; jt < NCHUNK; ++jt) {
        const int s = jt & 1;
        if (jt + 1 < NCHUNK) {
            load_B(jt + 1, s ^ 1);
            cp_commit();
            gen_A(jt + 1, s ^ 1);
        }

        #pragma unroll
        for (int kk = 0; kk < 4; kk++) {
            uint32_t ah[2][4];
            #pragma unroll
            for (int mt = 0; mt < 2; mt++)
                ldsm4(ah[mt], sb + AOFF[s] + sw128((uint32_t)(
                    (wm * 32 + mt * 16 + aRow) * 128 + kk * 32 + aH * 16)));
            uint32_t bh[4][4];
            #pragma unroll
            for (int p = 0; p < 4; p++)
                ldsm4(bh[p], sb + BOFF[s] + sw128((uint32_t)(
                    (wn * 64 + p * 16 + bRow) * 128 + kk * 32 + bH * 16)));
            #pragma unroll
            for (int mt = 0; mt < 2; mt++)
                #pragma unroll
                for (int p = 0; p < 4; p++) {
                    mma16816(acc[mt][2 * p],     ah[mt], bh[p][0], bh[p][1]);
                    mma16816(acc[mt][2 * p + 1], ah[mt], bh[p][2], bh[p][3]);
                }
        }

        if (jt + 1 < NCHUNK) cp_wait0();
        __syncthreads();
    }

    // ---- epilogue: partial numerators + partial Z ----
    {
        float* npb = g_np + (size_t)ks * NN * DOUT;
        const int g  = lane >> 2;
        const int tg = lane & 3;
        #pragma unroll
        for (int mt = 0; mt < 2; mt++)
            #pragma unroll
            for (int nt = 0; nt < 8; nt++) {
                const int r0  = i0 + wm * 32 + mt * 16 + g;
                const int col = wn * 64 + nt * 8 + tg * 2;
                *(float2*)(npb + (size_t)r0 * DOUT + col) =
                    make_float2(acc[mt][nt][0], acc[mt][nt][1]);
                *(float2*)(npb + (size_t)(r0 + 8) * DOUT + col) =
                    make_float2(acc[mt][nt][2], acc[mt][nt][3]);
            }
    }
    float* zb = (float*)(smem + ZOFF);
    zb[tid] = zacc;
    __syncthreads();
    if (tid < 64)
        g_zp[ks * NN + i0 + tid] =
            zb[4 * tid] + zb[4 * tid + 1] + zb[4 * tid + 2] + zb[4 * tid + 3];
}

// ---------------------------------------------------------------------------
// k_combine: sum partials, softmax-normalize, ELU
// ---------------------------------------------------------------------------
__global__ void k_combine(float* __restrict__ out)
{
    const int row = blockIdx.x;
    const int c = threadIdx.x * 4;
    const float inv = 1.f / (g_zp[row] + g_zp[NN + row]);
    float4 p0 = *(const float4*)&g_np[(size_t)row * DOUT + c];
    float4 p1 = *(const float4*)&g_np[(size_t)(NN + row) * DOUT + c];
    float v[4] = {(p0.x + p1.x) * inv, (p0.y + p1.y) * inv,
                  (p0.z + p1.z) * inv, (p0.w + p1.w) * inv};
    #pragma unroll
    for (int q = 0; q < 4; q++)
        v[q] = (v[q] > 0.f) ? v[q] : expm1f(v[q]);
    *(float4*)&out[(size_t)row * DOUT + c] = make_float4(v[0], v[1], v[2], v[3]);
}

// ---------------------------------------------------------------------------
extern "C" void kernel_launch(void* const* d_in, const int* in_sizes, int n_in,
                              void* d_out, int out_size)
{
    const float* h   = (const float*)d_in[0];   // [8192, 512]
    const int*   adj = (const int*)  d_in[1];   // [8192, 8192]
    const float* W   = (const float*)d_in[2];   // [512, 256]
    const float* a   = (const float*)d_in[3];   // [512, 1]
    float* out = (float*)d_out;                 // [8192, 256]

    cudaFuncSetAttribute(k_hwt, cudaFuncAttributeMaxDynamicSharedMemorySize,
                         SMEM_TOTAL);
    cudaFuncSetAttribute(k_gat_mma, cudaFuncAttributeMaxDynamicSharedMemorySize,
                         SMEM_TOTAL);

    k_conv_h<<<NN * DIN / (256 * 8), 256>>>(h);
    k_prep_w<<<1, 512>>>(W, a);
    k_f1f2h<<<NN / 8, dim3(32, 8)>>>(h);
    k_E<<<NN / 1024, 1024>>>();
    k_hwt<<<NN / 64, 256, SMEM_TOTAL>>>();
    k_gat_mma<<<dim3(NN / 64, KSLICES), 256, SMEM_TOTAL>>>(adj);
    k_combine<<<NN, 64>>>(out);
}

// round 13
// speedup vs baseline: 2.4709x; 2.4709x over previous
#include <cuda_runtime.h>
#include <cuda_bf16.h>
#include <cstdint>

#define NN   8192
#define DIN  512
#define DOUT 256
#define KSLICES 2
#define KSL  (NN / KSLICES)     // 4096 k per slice
#define KT   64                 // k per chunk
#define NCHUNK (KSL / KT)       // 64

// ---------------- scratch (__device__ globals: allocation-free rule) --------
__device__ float          g_hW  [(size_t)NN * DOUT];      // fp32 hW (for f1f2)
__device__ float          g_f1  [NN];
__device__ float          g_f2  [NN];
__device__ unsigned       g_fmax_u;                        // ordered-uint max(f2)
__device__ unsigned short g_hWT [(size_t)DOUT * NN];      // hW^T fp16 [col][row]
__device__ float          g_np  [(size_t)KSLICES * NN * DOUT]; // partial numerators
__device__ float          g_zp  [KSLICES * NN];                // partial Z

// ---------------- helpers ---------------------------------------------------
__device__ __forceinline__ uint32_t smem_u32(const void* p) {
    uint32_t a;
    asm("{ .reg .u64 t; cvta.to.shared.u64 t, %1; cvt.u32.u64 %0, t; }"
        : "=r"(a) : "l"(p));
    return a;
}
__device__ __forceinline__ uint32_t sw128(uint32_t off) {
    return off ^ ((off >> 3) & 0x70);
}
// packs (lo, hi) -> low 16 = f16(lo), high 16 = f16(hi)
__device__ __forceinline__ unsigned pack_f16x2(float lo, float hi) {
    unsigned r;
    asm("cvt.rn.f16x2.f32 %0, %1, %2;" : "=r"(r) : "f"(hi), "f"(lo));
    return r;
}
__device__ __forceinline__ void cp16(uint32_t smem, const void* g) {
    asm volatile("cp.async.cg.shared.global [%0], [%1], 16;"
                 :: "r"(smem), "l"(g));
}
__device__ __forceinline__ void cp_commit() {
    asm volatile("cp.async.commit_group;");
}
__device__ __forceinline__ void cp_wait0() {
    asm volatile("cp.async.wait_group 0;" ::: "memory");
}
__device__ __forceinline__ void ldsm4(uint32_t* r, uint32_t addr) {
    asm volatile("ldmatrix.sync.aligned.m8n8.x4.shared.b16 {%0,%1,%2,%3}, [%4];"
                 : "=r"(r[0]), "=r"(r[1]), "=r"(r[2]), "=r"(r[3]) : "r"(addr));
}
__device__ __forceinline__ void mma16816(float* c, const uint32_t* a,
                                         uint32_t b0, uint32_t b1) {
    asm volatile(
        "mma.sync.aligned.m16n8k16.row.col.f32.f16.f16.f32 "
        "{%0,%1,%2,%3},{%4,%5,%6,%7},{%8,%9},{%0,%1,%2,%3};"
        : "+f"(c[0]), "+f"(c[1]), "+f"(c[2]), "+f"(c[3])
        : "r"(a[0]), "r"(a[1]), "r"(a[2]), "r"(a[3]), "r"(b0), "r"(b1));
}
// ordered-uint encoding for float atomicMax (monotone for all floats)
__device__ __forceinline__ unsigned f2ord(float x) {
    unsigned b = __float_as_uint(x);
    return (b & 0x80000000u) ? ~b : (b | 0x80000000u);
}
__device__ __forceinline__ float ord2f(unsigned u) {
    unsigned b = (u & 0x80000000u) ? (u & 0x7fffffffu) : ~u;
    return __uint_as_float(b);
}

// ---------------------------------------------------------------------------
// Kernel A: g_hW = h @ W  (fp32)  +  epilogue: g_hWT fp16 (transposed)
// 128x64 tile, 256 threads, 8x4 micro-tile.  Also resets g_fmax_u.
// ---------------------------------------------------------------------------
__global__ __launch_bounds__(256) void k_gemm_hw(
    const float* __restrict__ h, const float* __restrict__ W)
{
    __shared__ float As[32][128];  // [k][m] 16 KB
    __shared__ float Bs[32][64];   // [k][n]  8 KB

    const int tid = threadIdx.x;
    const int c0  = blockIdx.x * 64;
    const int i0  = blockIdx.y * 128;
    const int tx  = tid & 15;            // 4 cols
    const int ty  = tid >> 4;            // 8 rows

    const int li  = tid >> 1;            // 0..127 A-load row
    const int lk  = (tid & 1) * 16;      // A-load k base (16 k's)

    const int bk  = tid >> 3;            // 0..31  B-load k
    const int bc  = (tid & 7) * 8;       // B-load col (8 cols)

    if (blockIdx.x == 0 && blockIdx.y == 0 && tid == 0)
        g_fmax_u = 0u;                   // ordered-uint of -inf (reset per call)

    float acc[8][4] = {};

    for (int k0 = 0; k0 < DIN; k0 += 32) {
        float4 a0 = *(const float4*)&h[(i0 + li) * DIN + k0 + lk];
        float4 a1 = *(const float4*)&h[(i0 + li) * DIN + k0 + lk + 4];
        float4 a2 = *(const float4*)&h[(i0 + li) * DIN + k0 + lk + 8];
        float4 a3 = *(const float4*)&h[(i0 + li) * DIN + k0 + lk + 12];
        float4 b0 = *(const float4*)&W[(k0 + bk) * DOUT + c0 + bc];
        float4 b1 = *(const float4*)&W[(k0 + bk) * DOUT + c0 + bc + 4];

        __syncthreads();
        As[lk +  0][li] = a0.x; As[lk +  1][li] = a0.y;
        As[lk +  2][li] = a0.z; As[lk +  3][li] = a0.w;
        As[lk +  4][li] = a1.x; As[lk +  5][li] = a1.y;
        As[lk +  6][li] = a1.z; As[lk +  7][li] = a1.w;
        As[lk +  8][li] = a2.x; As[lk +  9][li] = a2.y;
        As[lk + 10][li] = a2.z; As[lk + 11][li] = a2.w;
        As[lk + 12][li] = a3.x; As[lk + 13][li] = a3.y;
        As[lk + 14][li] = a3.z; As[lk + 15][li] = a3.w;
        *(float4*)&Bs[bk][bc]     = b0;
        *(float4*)&Bs[bk][bc + 4] = b1;
        __syncthreads();

        #pragma unroll
        for (int k = 0; k < 32; k++) {
            float4 af0 = *(const float4*)&As[k][ty * 8];
            float4 af1 = *(const float4*)&As[k][ty * 8 + 4];
            float4 bf  = *(const float4*)&Bs[k][tx * 4];
            float ar[8] = {af0.x, af0.y, af0.z, af0.w,
                           af1.x, af1.y, af1.z, af1.w};
            float br[4] = {bf.x, bf.y, bf.z, bf.w};
            #pragma unroll
            for (int r = 0; r < 8; r++)
                #pragma unroll
                for (int c = 0; c < 4; c++)
                    acc[r][c] = fmaf(ar[r], br[c], acc[r][c]);
        }
    }

    #pragma unroll
    for (int r = 0; r < 8; r++) {
        float4 v = make_float4(acc[r][0], acc[r][1], acc[r][2], acc[r][3]);
        *(float4*)&g_hW[(size_t)(i0 + ty * 8 + r) * DOUT + c0 + tx * 4] = v;
    }
    // transposed fp16: 8 rows per column -> one uint4
    #pragma unroll
    for (int cc = 0; cc < 4; cc++) {
        const int c = c0 + tx * 4 + cc;
        uint4 p;
        p.x = pack_f16x2(acc[0][cc], acc[1][cc]);
        p.y = pack_f16x2(acc[2][cc], acc[3][cc]);
        p.z = pack_f16x2(acc[4][cc], acc[5][cc]);
        p.w = pack_f16x2(acc[6][cc], acc[7][cc]);
        *(uint4*)(g_hWT + (size_t)c * NN + i0 + ty * 8) = p;
    }
}

// ---------------------------------------------------------------------------
// Kernel B: f1 = hW @ a[:256],  f2 = hW @ a[256:]  + fused atomic max(f2)
// ---------------------------------------------------------------------------
__global__ void k_f1f2(const float* __restrict__ a)
{
    const int row  = blockIdx.x * 8 + threadIdx.y;
    const int lane = threadIdx.x;
    const float* hw = &g_hW[(size_t)row * DOUT];

    float s1 = 0.f, s2 = 0.f;
    #pragma unroll
    for (int c = 0; c < DOUT; c += 32) {
        float v = hw[c + lane];
        s1 = fmaf(v, a[c + lane], s1);
        s2 = fmaf(v, a[DOUT + c + lane], s2);
    }
    #pragma unroll
    for (int off = 16; off; off >>= 1) {
        s1 += __shfl_xor_sync(0xffffffffu, s1, off);
        s2 += __shfl_xor_sync(0xffffffffu, s2, off);
    }
    if (lane == 0) {
        g_f1[row] = s1;
        g_f2[row] = s2;
        atomicMax(&g_fmax_u, f2ord(s2));
    }
}

// ---------------------------------------------------------------------------
// Kernel C: warp-MMA (mma.sync fp16) masked-softmax aggregation.
// EXACT R5 structure: M=64 x N=256 CTA tile, 256 threads (8 warps, 2m x 4n),
// 2 CTAs/SM, grid (128, 2). MUFU exp in gen_A (register-lean; spill-free).
// ---------------------------------------------------------------------------
// SMEM: [0..1KB) zbuf; stages at 2KB: per stage A 8K | B 32K
#define ZOFF        0
#define TILE0       2048
#define STAGE_BYTES 40960
#define SMEM_TOTAL  (TILE0 + 2 * STAGE_BYTES)

__global__ __launch_bounds__(256, 2) void k_gat_mma(const int* __restrict__ adj)
{
    extern __shared__ __align__(1024) char smem[];
    const uint32_t sb = smem_u32(smem);

    const int tid  = threadIdx.x;
    const int lane = tid & 31;
    const int wid  = tid >> 5;
    const int wm   = wid & 1;      // warp row  (32 rows)
    const int wn   = wid >> 1;     // warp col  (64 cols)
    const int i0   = blockIdx.x * 64;
    const int ks   = blockIdx.y;
    const int k0s  = ks * KSL;

    int AHI[2], BHI[2];
    #pragma unroll
    for (int s = 0; s < 2; s++) {
        AHI[s] = TILE0 + s * STAGE_BYTES;
        BHI[s] = AHI[s] + 8192;
    }

    // ---- w-gen mapping: row iw, 16 k's starting at kb ----
    const int iw = tid >> 2;             // 0..63
    const int kb = (tid & 3) * 16;
    const float f1v  = g_f1[i0 + iw];
    const float smax = f1v + ord2f(g_fmax_u);
    const float Mrow = fmaxf(smax, 0.2f * smax);   // leaky(f1+Fmax) >= all e
    float zacc = 0.f;

    // ---- B cp.async mapping: n-row = tid, 8 chunks of 16B ----
    const int rB = tid;

    float acc[2][8][4];
    #pragma unroll
    for (int mt = 0; mt < 2; mt++)
        #pragma unroll
        for (int nt = 0; nt < 8; nt++)
            #pragma unroll
            for (int q = 0; q < 4; q++) acc[mt][nt][q] = 0.f;

    auto load_B = [&](int jt, int s) {
        const size_t gk = (size_t)rB * NN + k0s + jt * KT;
        #pragma unroll
        for (int cc = 0; cc < 8; cc++) {
            const uint32_t off = sw128((uint32_t)(rB * 128 + cc * 16));
            cp16(sb + BHI[s] + off, g_hWT + gk + cc * 8);
        }
    };

    auto gen_A = [&](int jt, int s) {
        const size_t kg = (size_t)k0s + jt * KT + kb;
        const int4*   ap = (const int4*)  (adj  + (size_t)(i0 + iw) * NN + kg);
        const float4* fp = (const float4*)(g_f2 + kg);
        int4   A0 = ap[0], A1 = ap[1], A2 = ap[2], A3 = ap[3];
        float4 F0 = fp[0], F1 = fp[1], F2 = fp[2], F3 = fp[3];
        const int   av[16] = {A0.x,A0.y,A0.z,A0.w, A1.x,A1.y,A1.z,A1.w,
                              A2.x,A2.y,A2.z,A2.w, A3.x,A3.y,A3.z,A3.w};
        const float fv[16] = {F0.x,F0.y,F0.z,F0.w, F1.x,F1.y,F1.z,F1.w,
                              F2.x,F2.y,F2.z,F2.w, F3.x,F3.y,F3.z,F3.w};
        float w[16];
        #pragma unroll
        for (int q = 0; q < 16; q++) {
            float sv = f1v + fv[q];
            float e  = fmaxf(sv, 0.2f * sv);     // leaky
            float we = __expf(e - Mrow);         // in (0,1]
            w[q] = (av[q] > 0) ? we : 0.f;
            zacc += w[q];
        }
        uint4 H0, H1;
        H0.x = pack_f16x2(w[0],  w[1]);  H0.y = pack_f16x2(w[2],  w[3]);
        H0.z = pack_f16x2(w[4],  w[5]);  H0.w = pack_f16x2(w[6],  w[7]);
        H1.x = pack_f16x2(w[8],  w[9]);  H1.y = pack_f16x2(w[10], w[11]);
        H1.z = pack_f16x2(w[12], w[13]); H1.w = pack_f16x2(w[14], w[15]);
        const uint32_t o0 = sw128((uint32_t)(iw * 128 + kb * 2));
        const uint32_t o1 = sw128((uint32_t)(iw * 128 + kb * 2 + 16));
        *(uint4*)(smem + AHI[s] + o0) = H0;
        *(uint4*)(smem + AHI[s] + o1) = H1;
    };

    // ldmatrix lane address components
    const int aRow = lane & 15;                        // A: row within 16-tile
    const int aH   = lane >> 4;                        // A: k-half
    const int bRow = (lane & 7) | ((lane >> 4) << 3);  // B: n-row within 16
    const int bH   = (lane >> 3) & 1;                  // B: k-half

    // ---- prologue: fill stage 0 ----
    load_B(0, 0);
    cp_commit();
    gen_A(0, 0);
    cp_wait0();
    __syncthreads();

    #pragma unroll 1
    for (int jt = 0; jt < NCHUNK; ++jt) {
        const int s = jt & 1;
        if (jt + 1 < NCHUNK) {
            load_B(jt + 1, s ^ 1);
            cp_commit();
            gen_A(jt + 1, s ^ 1);
        }

        // ---- MMA on stage s ----
        #pragma unroll
        for (int kk = 0; kk < 4; kk++) {
            uint32_t ah[2][4];
            #pragma unroll
            for (int mt = 0; mt < 2; mt++)
                ldsm4(ah[mt], sb + AHI[s] + sw128((uint32_t)(
                    (wm * 32 + mt * 16 + aRow) * 128 + kk * 32 + aH * 16)));
            uint32_t bh[4][4];
            #pragma unroll
            for (int p = 0; p < 4; p++)
                ldsm4(bh[p], sb + BHI[s] + sw128((uint32_t)(
                    (wn * 64 + p * 16 + bRow) * 128 + kk * 32 + bH * 16)));
            #pragma unroll
            for (int mt = 0; mt < 2; mt++)
                #pragma unroll
                for (int p = 0; p < 4; p++) {
                    mma16816(acc[mt][2 * p],     ah[mt], bh[p][0], bh[p][1]);
                    mma16816(acc[mt][2 * p + 1], ah[mt], bh[p][2], bh[p][3]);
                }
        }

        if (jt + 1 < NCHUNK) cp_wait0();
        __syncthreads();
    }

    // ---- epilogue: partial numerators + partial Z ----
    {
        float* npb = g_np + (size_t)ks * NN * DOUT;
        const int g  = lane >> 2;
        const int tg = lane & 3;
        #pragma unroll
        for (int mt = 0; mt < 2; mt++)
            #pragma unroll
            for (int nt = 0; nt < 8; nt++) {
                const int r0  = i0 + wm * 32 + mt * 16 + g;
                const int col = wn * 64 + nt * 8 + tg * 2;
                *(float2*)(npb + (size_t)r0 * DOUT + col) =
                    make_float2(acc[mt][nt][0], acc[mt][nt][1]);
                *(float2*)(npb + (size_t)(r0 + 8) * DOUT + col) =
                    make_float2(acc[mt][nt][2], acc[mt][nt][3]);
            }
    }
    float* zb = (float*)(smem + ZOFF);
    zb[tid] = zacc;
    __syncthreads();
    if (tid < 64)
        g_zp[ks * NN + i0 + tid] =
            zb[4 * tid] + zb[4 * tid + 1] + zb[4 * tid + 2] + zb[4 * tid + 3];
}

// ---------------------------------------------------------------------------
// Kernel D: combine partials, softmax-normalize, ELU
// ---------------------------------------------------------------------------
__global__ void k_combine(float* __restrict__ out)
{
    const int row = blockIdx.x;
    const int c = threadIdx.x * 4;
    const float inv = 1.f / (g_zp[row] + g_zp[NN + row]);
    float4 p0 = *(const float4*)&g_np[(size_t)row * DOUT + c];
    float4 p1 = *(const float4*)&g_np[(size_t)(NN + row) * DOUT + c];
    float v[4] = {(p0.x + p1.x) * inv, (p0.y + p1.y) * inv,
                  (p0.z + p1.z) * inv, (p0.w + p1.w) * inv};
    #pragma unroll
    for (int q = 0; q < 4; q++)
        v[q] = (v[q] > 0.f) ? v[q] : expm1f(v[q]);
    *(float4*)&out[(size_t)row * DOUT + c] = make_float4(v[0], v[1], v[2], v[3]);
}

// ---------------------------------------------------------------------------
extern "C" void kernel_launch(void* const* d_in, const int* in_sizes, int n_in,
                              void* d_out, int out_size)
{
    const float* h   = (const float*)d_in[0];   // [8192, 512]
    const int*   adj = (const int*)  d_in[1];   // [8192, 8192]
    const float* W   = (const float*)d_in[2];   // [512, 256]
    const float* a   = (const float*)d_in[3];   // [512, 1]
    float* out = (float*)d_out;                 // [8192, 256]

    cudaFuncSetAttribute(k_gat_mma, cudaFuncAttributeMaxDynamicSharedMemorySize,
                         SMEM_TOTAL);

    k_gemm_hw<<<dim3(DOUT / 64, NN / 128), 256>>>(h, W);
    k_f1f2<<<NN / 8, dim3(32, 8)>>>(a);
    k_gat_mma<<<dim3(NN / 64, KSLICES), 256, SMEM_TOTAL>>>(adj);
    k_combine<<<NN, 64>>>(out);
}

// round 14
// speedup vs baseline: 2.8230x; 1.1425x over previous
#include <cuda_runtime.h>
#include <cuda_bf16.h>
#include <cstdint>

#define NN   8192
#define DIN  512
#define DOUT 256
#define KSLICES 2
#define KSL  (NN / KSLICES)     // 4096 k per slice
#define KT   64                 // k per chunk
#define NCHUNK (KSL / KT)       // 64
#define HNCH (DIN / KT)         // 8 chunks for hWT gemm

// ---------------- scratch (__device__ globals: allocation-free rule) --------
__device__ float          g_f1  [NN];
__device__ float          g_f2  [NN];
__device__ unsigned       g_fmax_u;                      // ordered-uint max(f2)
__device__ float          g_wa  [2 * DIN];               // W@a1, W@a2
__device__ unsigned short g_hh  [(size_t)NN * DIN];      // h fp16
__device__ unsigned short g_Wt  [(size_t)DOUT * DIN];    // W^T fp16 [c][k]
__device__ unsigned short g_hWT [(size_t)DOUT * NN];     // hW^T fp16 [c][i]
__device__ float          g_np  [(size_t)KSLICES * NN * DOUT]; // partial numerators
__device__ float          g_zp  [KSLICES * NN];                // partial Z

// ---------------- helpers ---------------------------------------------------
__device__ __forceinline__ uint32_t smem_u32(const void* p) {
    uint32_t a;
    asm("{ .reg .u64 t; cvta.to.shared.u64 t, %1; cvt.u32.u64 %0, t; }"
        : "=r"(a) : "l"(p));
    return a;
}
__device__ __forceinline__ uint32_t sw128(uint32_t off) {
    return off ^ ((off >> 3) & 0x70);
}
// packs (lo, hi) -> low 16 = f16(lo), high 16 = f16(hi)
__device__ __forceinline__ unsigned pack_f16x2(float lo, float hi) {
    unsigned r;
    asm("cvt.rn.f16x2.f32 %0, %1, %2;" : "=r"(r) : "f"(hi), "f"(lo));
    return r;
}
__device__ __forceinline__ void cp16(uint32_t smem, const void* g) {
    asm volatile("cp.async.cg.shared.global [%0], [%1], 16;"
                 :: "r"(smem), "l"(g));
}
__device__ __forceinline__ void cp_commit() {
    asm volatile("cp.async.commit_group;");
}
__device__ __forceinline__ void cp_wait0() {
    asm volatile("cp.async.wait_group 0;" ::: "memory");
}
__device__ __forceinline__ void ldsm4(uint32_t* r, uint32_t addr) {
    asm volatile("ldmatrix.sync.aligned.m8n8.x4.shared.b16 {%0,%1,%2,%3}, [%4];"
                 : "=r"(r[0]), "=r"(r[1]), "=r"(r[2]), "=r"(r[3]) : "r"(addr));
}
__device__ __forceinline__ void mma16816(float* c, const uint32_t* a,
                                         uint32_t b0, uint32_t b1) {
    asm volatile(
        "mma.sync.aligned.m16n8k16.row.col.f32.f16.f16.f32 "
        "{%0,%1,%2,%3},{%4,%5,%6,%7},{%8,%9},{%0,%1,%2,%3};"
        : "+f"(c[0]), "+f"(c[1]), "+f"(c[2]), "+f"(c[3])
        : "r"(a[0]), "r"(a[1]), "r"(a[2]), "r"(a[3]), "r"(b0), "r"(b1));
}
// ordered-uint encoding for float atomicMax (monotone for all floats)
__device__ __forceinline__ unsigned f2ord(float x) {
    unsigned b = __float_as_uint(x);
    return (b & 0x80000000u) ? ~b : (b | 0x80000000u);
}
__device__ __forceinline__ float ord2f(unsigned u) {
    unsigned b = (u & 0x80000000u) ? (u & 0x7fffffffu) : ~u;
    return __uint_as_float(b);
}

// SMEM map shared by k_hwt / k_gat: [0..2KB) scratch; 2 stages of A 8K | B 32K
#define ZOFF        0
#define TILE0       2048
#define STAGE_BYTES 40960
#define SMEM_TOTAL  (TILE0 + 2 * STAGE_BYTES)

// ---------------------------------------------------------------------------
// k_conv_h: h fp32 -> g_hh fp16; block 0 also resets g_fmax_u.
// ---------------------------------------------------------------------------
__global__ void k_conv_h(const float* __restrict__ h)
{
    if (blockIdx.x == 0 && threadIdx.x == 0) g_fmax_u = 0u;
    const size_t i = ((size_t)blockIdx.x * 256 + threadIdx.x) * 8;
    float4 a = *(const float4*)(h + i);
    float4 b = *(const float4*)(h + i + 4);
    uint4 o;
    o.x = pack_f16x2(a.x, a.y);
    o.y = pack_f16x2(a.z, a.w);
    o.z = pack_f16x2(b.x, b.y);
    o.w = pack_f16x2(b.z, b.w);
    *(uint4*)(g_hh + i) = o;
}

// ---------------------------------------------------------------------------
// k_prep_w: 64 blocks x 256 threads.
//   wa[k]      = sum_c W[k][c] * a1[c]   (and a2)   -- 8 k-rows per block
//   g_Wt[c][k] = fp16 W[k][c]                        -- strided copy
// ---------------------------------------------------------------------------
__global__ void k_prep_w(const float* __restrict__ W, const float* __restrict__ a)
{
    const int tid  = threadIdx.x;
    const int lane = tid & 31;
    const int wid  = tid >> 5;       // 0..7
    const int blk  = blockIdx.x;     // 0..63

    // wa: warp per k row
    const int k = blk * 8 + wid;
    {
        float s1 = 0.f, s2 = 0.f;
        #pragma unroll
        for (int c = lane; c < DOUT; c += 32) {
            float w = W[k * DOUT + c];
            s1 = fmaf(w, a[c], s1);
            s2 = fmaf(w, a[DOUT + c], s2);
        }
        #pragma unroll
        for (int o = 16; o; o >>= 1) {
            s1 += __shfl_xor_sync(~0u, s1, o);
            s2 += __shfl_xor_sync(~0u, s2, o);
        }
        if (lane == 0) { g_wa[k] = s1; g_wa[DIN + k] = s2; }
    }

    // Wt fp16 transpose: 131072 elems / (64*256) = 8 per thread
    for (int idx = blk * 256 + tid; idx < DIN * DOUT; idx += 64 * 256) {
        const int kk = idx >> 8;         // DOUT = 256
        const int cc = idx & 255;
        g_Wt[(size_t)cc * DIN + kk] =
            (unsigned short)(pack_f16x2(W[idx], 0.f) & 0xffff);
    }
}

// ---------------------------------------------------------------------------
// k_f1f2h: f1 = h @ wa1, f2 = h @ wa2 (fp32, warp per row) + atomic max(f2)
// ---------------------------------------------------------------------------
__global__ void k_f1f2h(const float* __restrict__ h)
{
    const int row  = blockIdx.x * 8 + threadIdx.y;
    const int lane = threadIdx.x;
    const float* hr = h + (size_t)row * DIN;

    float s1 = 0.f, s2 = 0.f;
    #pragma unroll
    for (int k = lane; k < DIN; k += 32) {
        float v = hr[k];
        s1 = fmaf(v, g_wa[k], s1);
        s2 = fmaf(v, g_wa[DIN + k], s2);
    }
    #pragma unroll
    for (int o = 16; o; o >>= 1) {
        s1 += __shfl_xor_sync(~0u, s1, o);
        s2 += __shfl_xor_sync(~0u, s2, o);
    }
    if (lane == 0) {
        g_f1[row] = s1;
        g_f2[row] = s2;
        atomicMax(&g_fmax_u, f2ord(s2));
    }
}

// ---------------------------------------------------------------------------
// k_hwt: g_hWT[c][i] = fp16( h @ W )^T via fp16 tensor MMA (R11-proven).
// 64(i) x 256(c) tile, 256 thr, 8 warps 2m x 4n, K=512 in 8 chunks.
// ---------------------------------------------------------------------------
__global__ __launch_bounds__(256, 2) void k_hwt()
{
    extern __shared__ __align__(1024) char smem[];
    const uint32_t sb = smem_u32(smem);
    const int tid  = threadIdx.x;
    const int lane = tid & 31;
    const int wid  = tid >> 5;
    const int wm   = wid & 1;
    const int wn   = wid >> 1;
    const int i0   = blockIdx.x * 64;

    int AOFF[2], BOFF[2];
    #pragma unroll
    for (int s = 0; s < 2; s++) {
        AOFF[s] = TILE0 + s * STAGE_BYTES;
        BOFF[s] = AOFF[s] + 8192;
    }

    const int arow = tid >> 2, aseg = tid & 3;   // A loader
    const int rB = tid;                          // B loader (row c)

    auto load_stage = [&](int jt, int s) {
        const size_t ga = (size_t)(i0 + arow) * DIN + jt * KT + aseg * 16;
        cp16(sb + AOFF[s] + sw128((uint32_t)(arow * 128 + aseg * 32)),      g_hh + ga);
        cp16(sb + AOFF[s] + sw128((uint32_t)(arow * 128 + aseg * 32 + 16)), g_hh + ga + 8);
        const size_t gb = (size_t)rB * DIN + jt * KT;
        #pragma unroll
        for (int cc = 0; cc < 8; cc++)
            cp16(sb + BOFF[s] + sw128((uint32_t)(rB * 128 + cc * 16)), g_Wt + gb + cc * 8);
    };

    const int aRow = lane & 15;
    const int aH   = lane >> 4;
    const int bRow = (lane & 7) | ((lane >> 4) << 3);
    const int bH   = (lane >> 3) & 1;

    float acc[2][8][4];
    #pragma unroll
    for (int mt = 0; mt < 2; mt++)
        #pragma unroll
        for (int nt = 0; nt < 8; nt++)
            #pragma unroll
            for (int q = 0; q < 4; q++) acc[mt][nt][q] = 0.f;

    load_stage(0, 0);
    cp_commit();
    cp_wait0();
    __syncthreads();

    #pragma unroll 1
    for (int jt = 0; jt < HNCH; ++jt) {
        const int s = jt & 1;
        if (jt + 1 < HNCH) { load_stage(jt + 1, s ^ 1); cp_commit(); }

        #pragma unroll
        for (int kk = 0; kk < 4; kk++) {
            uint32_t ah[2][4];
            #pragma unroll
            for (int mt = 0; mt < 2; mt++)
                ldsm4(ah[mt], sb + AOFF[s] + sw128((uint32_t)(
                    (wm * 32 + mt * 16 + aRow) * 128 + kk * 32 + aH * 16)));
            uint32_t bh[4][4];
            #pragma unroll
            for (int p = 0; p < 4; p++)
                ldsm4(bh[p], sb + BOFF[s] + sw128((uint32_t)(
                    (wn * 64 + p * 16 + bRow) * 128 + kk * 32 + bH * 16)));
            #pragma unroll
            for (int mt = 0; mt < 2; mt++)
                #pragma unroll
                for (int p = 0; p < 4; p++) {
                    mma16816(acc[mt][2 * p],     ah[mt], bh[p][0], bh[p][1]);
                    mma16816(acc[mt][2 * p + 1], ah[mt], bh[p][2], bh[p][3]);
                }
        }

        if (jt + 1 < HNCH) cp_wait0();
        __syncthreads();
    }

    // ---- transpose epilogue: frags -> smem fp16 [i][c] (pitch 258) -> [c][i]
    #define TP 258
    unsigned short* buf = (unsigned short*)(smem + TILE0);
    {
        const int g  = lane >> 2;
        const int tg = lane & 3;
        #pragma unroll
        for (int mt = 0; mt < 2; mt++)
            #pragma unroll
            for (int nt = 0; nt < 8; nt++) {
                const int r0  = wm * 32 + mt * 16 + g;
                const int col = wn * 64 + nt * 8 + tg * 2;
                *(unsigned*)(buf + r0 * TP + col) =
                    pack_f16x2(acc[mt][nt][0], acc[mt][nt][1]);
                *(unsigned*)(buf + (r0 + 8) * TP + col) =
                    pack_f16x2(acc[mt][nt][2], acc[mt][nt][3]);
            }
    }
    __syncthreads();
    {
        uint32_t pk[32];
        #pragma unroll
        for (int q = 0; q < 32; q++) {
            unsigned lo = buf[(2 * q) * TP + tid];
            unsigned hi = buf[(2 * q + 1) * TP + tid];
            pk[q] = lo | (hi << 16);
        }
        unsigned short* dst = g_hWT + (size_t)tid * NN + i0;
        #pragma unroll
        for (int q = 0; q < 8; q++)
            *(uint4*)(dst + q * 8) =
                make_uint4(pk[4 * q], pk[4 * q + 1], pk[4 * q + 2], pk[4 * q + 3]);
    }
}

// ---------------------------------------------------------------------------
// k_gat_mma: EXACT R13 kernel (untouched). M=64 x N=256, 256 thr, 2 CTA/SM,
// grid (128, 2), MUFU exp in gen_A, single sync per chunk.
// ---------------------------------------------------------------------------
__global__ __launch_bounds__(256, 2) void k_gat_mma(const int* __restrict__ adj)
{
    extern __shared__ __align__(1024) char smem[];
    const uint32_t sb = smem_u32(smem);

    const int tid  = threadIdx.x;
    const int lane = tid & 31;
    const int wid  = tid >> 5;
    const int wm   = wid & 1;      // warp row  (32 rows)
    const int wn   = wid >> 1;     // warp col  (64 cols)
    const int i0   = blockIdx.x * 64;
    const int ks   = blockIdx.y;
    const int k0s  = ks * KSL;

    int AHI[2], BHI[2];
    #pragma unroll
    for (int s = 0; s < 2; s++) {
        AHI[s] = TILE0 + s * STAGE_BYTES;
        BHI[s] = AHI[s] + 8192;
    }

    // ---- w-gen mapping: row iw, 16 k's starting at kb ----
    const int iw = tid >> 2;             // 0..63
    const int kb = (tid & 3) * 16;
    const float f1v  = g_f1[i0 + iw];
    const float smax = f1v + ord2f(g_fmax_u);
    const float Mrow = fmaxf(smax, 0.2f * smax);   // leaky(f1+Fmax) >= all e
    float zacc = 0.f;

    // ---- B cp.async mapping: n-row = tid, 8 chunks of 16B ----
    const int rB = tid;

    float acc[2][8][4];
    #pragma unroll
    for (int mt = 0; mt < 2; mt++)
        #pragma unroll
        for (int nt = 0; nt < 8; nt++)
            #pragma unroll
            for (int q = 0; q < 4; q++) acc[mt][nt][q] = 0.f;

    auto load_B = [&](int jt, int s) {
        const size_t gk = (size_t)rB * NN + k0s + jt * KT;
        #pragma unroll
        for (int cc = 0; cc < 8; cc++) {
            const uint32_t off = sw128((uint32_t)(rB * 128 + cc * 16));
            cp16(sb + BHI[s] + off, g_hWT + gk + cc * 8);
        }
    };

    auto gen_A = [&](int jt, int s) {
        const size_t kg = (size_t)k0s + jt * KT + kb;
        const int4*   ap = (const int4*)  (adj  + (size_t)(i0 + iw) * NN + kg);
        const float4* fp = (const float4*)(g_f2 + kg);
        int4   A0 = ap[0], A1 = ap[1], A2 = ap[2], A3 = ap[3];
        float4 F0 = fp[0], F1 = fp[1], F2 = fp[2], F3 = fp[3];
        const int   av[16] = {A0.x,A0.y,A0.z,A0.w, A1.x,A1.y,A1.z,A1.w,
                              A2.x,A2.y,A2.z,A2.w, A3.x,A3.y,A3.z,A3.w};
        const float fv[16] = {F0.x,F0.y,F0.z,F0.w, F1.x,F1.y,F1.z,F1.w,
                              F2.x,F2.y,F2.z,F2.w, F3.x,F3.y,F3.z,F3.w};
        float w[16];
        #pragma unroll
        for (int q = 0; q < 16; q++) {
            float sv = f1v + fv[q];
            float e  = fmaxf(sv, 0.2f * sv);     // leaky
            float we = __expf(e - Mrow);         // in (0,1]
            w[q] = (av[q] > 0) ? we : 0.f;
            zacc += w[q];
        }
        uint4 H0, H1;
        H0.x = pack_f16x2(w[0],  w[1]);  H0.y = pack_f16x2(w[2],  w[3]);
        H0.z = pack_f16x2(w[4],  w[5]);  H0.w = pack_f16x2(w[6],  w[7]);
        H1.x = pack_f16x2(w[8],  w[9]);  H1.y = pack_f16x2(w[10], w[11]);
        H1.z = pack_f16x2(w[12], w[13]); H1.w = pack_f16x2(w[14], w[15]);
        const uint32_t o0 = sw128((uint32_t)(iw * 128 + kb * 2));
        const uint32_t o1 = sw128((uint32_t)(iw * 128 + kb * 2 + 16));
        *(uint4*)(smem + AHI[s] + o0) = H0;
        *(uint4*)(smem + AHI[s] + o1) = H1;
    };

    // ldmatrix lane address components
    const int aRow = lane & 15;                        // A: row within 16-tile
    const int aH   = lane >> 4;                        // A: k-half
    const int bRow = (lane & 7) | ((lane >> 4) << 3);  // B: n-row within 16
    const int bH   = (lane >> 3) & 1;                  // B: k-half

    // ---- prologue: fill stage 0 ----
    load_B(0, 0);
    cp_commit();
    gen_A(0, 0);
    cp_wait0();
    __syncthreads();

    #pragma unroll 1
    for (int jt = 0; jt < NCHUNK; ++jt) {
        const int s = jt & 1;
        if (jt + 1 < NCHUNK) {
            load_B(jt + 1, s ^ 1);
            cp_commit();
            gen_A(jt + 1, s ^ 1);
        }

        // ---- MMA on stage s ----
        #pragma unroll
        for (int kk = 0; kk < 4; kk++) {
            uint32_t ah[2][4];
            #pragma unroll
            for (int mt = 0; mt < 2; mt++)
                ldsm4(ah[mt], sb + AHI[s] + sw128((uint32_t)(
                    (wm * 32 + mt * 16 + aRow) * 128 + kk * 32 + aH * 16)));
            uint32_t bh[4][4];
            #pragma unroll
            for (int p = 0; p < 4; p++)
                ldsm4(bh[p], sb + BHI[s] + sw128((uint32_t)(
                    (wn * 64 + p * 16 + bRow) * 128 + kk * 32 + bH * 16)));
            #pragma unroll
            for (int mt = 0; mt < 2; mt++)
                #pragma unroll
                for (int p = 0; p < 4; p++) {
                    mma16816(acc[mt][2 * p],     ah[mt], bh[p][0], bh[p][1]);
                    mma16816(acc[mt][2 * p + 1], ah[mt], bh[p][2], bh[p][3]);
                }
        }

        if (jt + 1 < NCHUNK) cp_wait0();
        __syncthreads();
    }

    // ---- epilogue: partial numerators + partial Z ----
    {
        float* npb = g_np + (size_t)ks * NN * DOUT;
        const int g  = lane >> 2;
        const int tg = lane & 3;
        #pragma unroll
        for (int mt = 0; mt < 2; mt++)
            #pragma unroll
            for (int nt = 0; nt < 8; nt++) {
                const int r0  = i0 + wm * 32 + mt * 16 + g;
                const int col = wn * 64 + nt * 8 + tg * 2;
                *(float2*)(npb + (size_t)r0 * DOUT + col) =
                    make_float2(acc[mt][nt][0], acc[mt][nt][1]);
                *(float2*)(npb + (size_t)(r0 + 8) * DOUT + col) =
                    make_float2(acc[mt][nt][2], acc[mt][nt][3]);
            }
    }
    float* zb = (float*)(smem + ZOFF);
    zb[tid] = zacc;
    __syncthreads();
    if (tid < 64)
        g_zp[ks * NN + i0 + tid] =
            zb[4 * tid] + zb[4 * tid + 1] + zb[4 * tid + 2] + zb[4 * tid + 3];
}

// ---------------------------------------------------------------------------
// k_combine: sum partials, softmax-normalize, ELU
// ---------------------------------------------------------------------------
__global__ void k_combine(float* __restrict__ out)
{
    const int row = blockIdx.x;
    const int c = threadIdx.x * 4;
    const float inv = 1.f / (g_zp[row] + g_zp[NN + row]);
    float4 p0 = *(const float4*)&g_np[(size_t)row * DOUT + c];
    float4 p1 = *(const float4*)&g_np[(size_t)(NN + row) * DOUT + c];
    float v[4] = {(p0.x + p1.x) * inv, (p0.y + p1.y) * inv,
                  (p0.z + p1.z) * inv, (p0.w + p1.w) * inv};
    #pragma unroll
    for (int q = 0; q < 4; q++)
        v[q] = (v[q] > 0.f) ? v[q] : expm1f(v[q]);
    *(float4*)&out[(size_t)row * DOUT + c] = make_float4(v[0], v[1], v[2], v[3]);
}

// ---------------------------------------------------------------------------
extern "C" void kernel_launch(void* const* d_in, const int* in_sizes, int n_in,
                              void* d_out, int out_size)
{
    const float* h   = (const float*)d_in[0];   // [8192, 512]
    const int*   adj = (const int*)  d_in[1];   // [8192, 8192]
    const float* W   = (const float*)d_in[2];   // [512, 256]
    const float* a   = (const float*)d_in[3];   // [512, 1]
    float* out = (float*)d_out;                 // [8192, 256]

    cudaFuncSetAttribute(k_hwt, cudaFuncAttributeMaxDynamicSharedMemorySize,
                         SMEM_TOTAL);
    cudaFuncSetAttribute(k_gat_mma, cudaFuncAttributeMaxDynamicSharedMemorySize,
                         SMEM_TOTAL);

    k_conv_h<<<NN * DIN / (256 * 8), 256>>>(h);
    k_prep_w<<<64, 256>>>(W, a);
    k_f1f2h<<<NN / 8, dim3(32, 8)>>>(h);
    k_hwt<<<NN / 64, 256, SMEM_TOTAL>>>();
    k_gat_mma<<<dim3(NN / 64, KSLICES), 256, SMEM_TOTAL>>>(adj);
    k_combine<<<NN, 64>>>(out);
}

// round 15
// speedup vs baseline: 2.8680x; 1.0160x over previous
#include <cuda_runtime.h>
#include <cuda_bf16.h>
#include <cstdint>

#define NN   8192
#define DIN  512
#define DOUT 256
#define KSLICES 2
#define KSL  (NN / KSLICES)     // 4096 k per slice
#define KT   64                 // k per chunk
#define NCHUNK (KSL / KT)       // 64
#define HNCH (DIN / KT)         // 8 chunks for hWT gemm

// ---------------- scratch (__device__ globals: allocation-free rule) --------
__device__ float          g_f1  [NN];
__device__ float          g_f2  [NN];
__device__ unsigned       g_fmax_u;                      // ordered-uint max(f2)
__device__ float          g_wa  [2 * DIN];               // W@a1, W@a2
__device__ unsigned short g_hh  [(size_t)NN * DIN];      // h fp16
__device__ unsigned short g_Wt  [(size_t)DOUT * DIN];    // W^T fp16 [c][k]
__device__ unsigned short g_hWT [(size_t)DOUT * NN];     // hW^T fp16 [c][i]
__device__ float          g_np  [(size_t)KSLICES * NN * DOUT]; // partial numerators
__device__ float          g_zp  [KSLICES * NN];                // partial Z

// ---------------- helpers ---------------------------------------------------
__device__ __forceinline__ uint32_t smem_u32(const void* p) {
    uint32_t a;
    asm("{ .reg .u64 t; cvta.to.shared.u64 t, %1; cvt.u32.u64 %0, t; }"
        : "=r"(a) : "l"(p));
    return a;
}
__device__ __forceinline__ uint32_t sw128(uint32_t off) {
    return off ^ ((off >> 3) & 0x70);
}
// packs (lo, hi) -> low 16 = f16(lo), high 16 = f16(hi)
__device__ __forceinline__ unsigned pack_f16x2(float lo, float hi) {
    unsigned r;
    asm("cvt.rn.f16x2.f32 %0, %1, %2;" : "=r"(r) : "f"(hi), "f"(lo));
    return r;
}
__device__ __forceinline__ void cp16(uint32_t smem, const void* g) {
    asm volatile("cp.async.cg.shared.global [%0], [%1], 16;"
                 :: "r"(smem), "l"(g));
}
__device__ __forceinline__ void cp_commit() {
    asm volatile("cp.async.commit_group;");
}
__device__ __forceinline__ void cp_wait0() {
    asm volatile("cp.async.wait_group 0;" ::: "memory");
}
__device__ __forceinline__ void ldsm4(uint32_t* r, uint32_t addr) {
    asm volatile("ldmatrix.sync.aligned.m8n8.x4.shared.b16 {%0,%1,%2,%3}, [%4];"
                 : "=r"(r[0]), "=r"(r[1]), "=r"(r[2]), "=r"(r[3]) : "r"(addr));
}
__device__ __forceinline__ void mma16816(float* c, const uint32_t* a,
                                         uint32_t b0, uint32_t b1) {
    asm volatile(
        "mma.sync.aligned.m16n8k16.row.col.f32.f16.f16.f32 "
        "{%0,%1,%2,%3},{%4,%5,%6,%7},{%8,%9},{%0,%1,%2,%3};"
        : "+f"(c[0]), "+f"(c[1]), "+f"(c[2]), "+f"(c[3])
        : "r"(a[0]), "r"(a[1]), "r"(a[2]), "r"(a[3]), "r"(b0), "r"(b1));
}
// ordered-uint encoding for float atomicMax (monotone for all floats)
__device__ __forceinline__ unsigned f2ord(float x) {
    unsigned b = __float_as_uint(x);
    return (b & 0x80000000u) ? ~b : (b | 0x80000000u);
}
__device__ __forceinline__ float ord2f(unsigned u) {
    unsigned b = (u & 0x80000000u) ? (u & 0x7fffffffu) : ~u;
    return __uint_as_float(b);
}

// SMEM maps
#define ZOFF        0
#define TILE0       2048
#define STAGE_BYTES 40960                      // gat: A 8K | B 32K
#define SMEM_TOTAL  (TILE0 + 2 * STAGE_BYTES)
#define HSTAGE      24576                      // hwt: A 8K | B 16K
#define SMEM_HWT    (TILE0 + 2 * HSTAGE)

// ---------------------------------------------------------------------------
// k_conv_h: h fp32 -> g_hh fp16; block 0 also resets g_fmax_u.
// ---------------------------------------------------------------------------
__global__ void k_conv_h(const float* __restrict__ h)
{
    if (blockIdx.x == 0 && threadIdx.x == 0) g_fmax_u = 0u;
    const size_t i = ((size_t)blockIdx.x * 256 + threadIdx.x) * 8;
    float4 a = *(const float4*)(h + i);
    float4 b = *(const float4*)(h + i + 4);
    uint4 o;
    o.x = pack_f16x2(a.x, a.y);
    o.y = pack_f16x2(a.z, a.w);
    o.z = pack_f16x2(b.x, b.y);
    o.w = pack_f16x2(b.z, b.w);
    *(uint4*)(g_hh + i) = o;
}

// ---------------------------------------------------------------------------
// k_prep_w: 64 blocks x 256 threads.
//   wa[k]      = sum_c W[k][c] * a1[c]   (and a2)   -- 8 k-rows per block
//   g_Wt[c][k] = fp16 W[k][c]                        -- strided copy
// ---------------------------------------------------------------------------
__global__ void k_prep_w(const float* __restrict__ W, const float* __restrict__ a)
{
    const int tid  = threadIdx.x;
    const int lane = tid & 31;
    const int wid  = tid >> 5;       // 0..7
    const int blk  = blockIdx.x;     // 0..63

    const int k = blk * 8 + wid;
    {
        float s1 = 0.f, s2 = 0.f;
        #pragma unroll
        for (int c = lane; c < DOUT; c += 32) {
            float w = W[k * DOUT + c];
            s1 = fmaf(w, a[c], s1);
            s2 = fmaf(w, a[DOUT + c], s2);
        }
        #pragma unroll
        for (int o = 16; o; o >>= 1) {
            s1 += __shfl_xor_sync(~0u, s1, o);
            s2 += __shfl_xor_sync(~0u, s2, o);
        }
        if (lane == 0) { g_wa[k] = s1; g_wa[DIN + k] = s2; }
    }

    for (int idx = blk * 256 + tid; idx < DIN * DOUT; idx += 64 * 256) {
        const int kk = idx >> 8;         // DOUT = 256
        const int cc = idx & 255;
        g_Wt[(size_t)cc * DIN + kk] =
            (unsigned short)(pack_f16x2(W[idx], 0.f) & 0xffff);
    }
}

// ---------------------------------------------------------------------------
// k_f1f2h: f1 = h @ wa1, f2 = h @ wa2 (fp32, warp per row) + atomic max(f2)
// ---------------------------------------------------------------------------
__global__ void k_f1f2h(const float* __restrict__ h)
{
    const int row  = blockIdx.x * 8 + threadIdx.y;
    const int lane = threadIdx.x;
    const float* hr = h + (size_t)row * DIN;

    float s1 = 0.f, s2 = 0.f;
    #pragma unroll
    for (int k = lane; k < DIN; k += 32) {
        float v = hr[k];
        s1 = fmaf(v, g_wa[k], s1);
        s2 = fmaf(v, g_wa[DIN + k], s2);
    }
    #pragma unroll
    for (int o = 16; o; o >>= 1) {
        s1 += __shfl_xor_sync(~0u, s1, o);
        s2 += __shfl_xor_sync(~0u, s2, o);
    }
    if (lane == 0) {
        g_f1[row] = s1;
        g_f2[row] = s2;
        atomicMax(&g_fmax_u, f2ord(s2));
    }
}

// ---------------------------------------------------------------------------
// k_hwt: g_hWT[c][i] = fp16( h @ W )^T via fp16 tensor MMA.
// R15: split N -> 64(i) x 128(c) tiles, grid (2, 128) = 256 CTAs, 2/SM.
// 8 warps 2m x 4n (each 32 rows x 32 cols), K=512 in 8 chunks.
// ---------------------------------------------------------------------------
__global__ __launch_bounds__(256, 2) void k_hwt()
{
    extern __shared__ __align__(1024) char smem[];
    const uint32_t sb = smem_u32(smem);
    const int tid  = threadIdx.x;
    const int lane = tid & 31;
    const int wid  = tid >> 5;
    const int wm   = wid & 1;        // 32-row half
    const int wn   = wid >> 1;       // 0..3, 32 cols each
    const int c0   = blockIdx.x * 128;
    const int i0   = blockIdx.y * 64;

    int AOFF[2], BOFF[2];
    #pragma unroll
    for (int s = 0; s < 2; s++) {
        AOFF[s] = TILE0 + s * HSTAGE;
        BOFF[s] = AOFF[s] + 8192;
    }

    const int arow = tid >> 2, aseg = tid & 3;   // A loader (2 cp16)
    const int rB2  = tid >> 1;                   // B local col-row 0..127
    const int hB   = (tid & 1) * 4;              // 4 cp16 each

    auto load_stage = [&](int jt, int s) {
        const size_t ga = (size_t)(i0 + arow) * DIN + jt * KT + aseg * 16;
        cp16(sb + AOFF[s] + sw128((uint32_t)(arow * 128 + aseg * 32)),      g_hh + ga);
        cp16(sb + AOFF[s] + sw128((uint32_t)(arow * 128 + aseg * 32 + 16)), g_hh + ga + 8);
        const size_t gb = (size_t)(c0 + rB2) * DIN + jt * KT;
        #pragma unroll
        for (int q = 0; q < 4; q++) {
            const int cc = hB + q;
            cp16(sb + BOFF[s] + sw128((uint32_t)(rB2 * 128 + cc * 16)),
                 g_Wt + gb + cc * 8);
        }
    };

    const int aRow = lane & 15;
    const int aH   = lane >> 4;
    const int bRow = (lane & 7) | ((lane >> 4) << 3);
    const int bH   = (lane >> 3) & 1;

    float acc[2][4][4];
    #pragma unroll
    for (int mt = 0; mt < 2; mt++)
        #pragma unroll
        for (int nt = 0; nt < 4; nt++)
            #pragma unroll
            for (int q = 0; q < 4; q++) acc[mt][nt][q] = 0.f;

    load_stage(0, 0);
    cp_commit();
    cp_wait0();
    __syncthreads();

    #pragma unroll 1
    for (int jt = 0; jt < HNCH; ++jt) {
        const int s = jt & 1;
        if (jt + 1 < HNCH) { load_stage(jt + 1, s ^ 1); cp_commit(); }

        #pragma unroll
        for (int kk = 0; kk < 4; kk++) {
            uint32_t ah[2][4];
            #pragma unroll
            for (int mt = 0; mt < 2; mt++)
                ldsm4(ah[mt], sb + AOFF[s] + sw128((uint32_t)(
                    (wm * 32 + mt * 16 + aRow) * 128 + kk * 32 + aH * 16)));
            uint32_t bh[2][4];
            #pragma unroll
            for (int p = 0; p < 2; p++)
                ldsm4(bh[p], sb + BOFF[s] + sw128((uint32_t)(
                    (wn * 32 + p * 16 + bRow) * 128 + kk * 32 + bH * 16)));
            #pragma unroll
            for (int mt = 0; mt < 2; mt++)
                #pragma unroll
                for (int p = 0; p < 2; p++) {
                    mma16816(acc[mt][2 * p],     ah[mt], bh[p][0], bh[p][1]);
                    mma16816(acc[mt][2 * p + 1], ah[mt], bh[p][2], bh[p][3]);
                }
        }

        if (jt + 1 < HNCH) cp_wait0();
        __syncthreads();
    }

    // ---- transpose epilogue: frags -> smem fp16 [i][c] (pitch 130) -> [c][i]
    #define TP2 130
    unsigned short* buf = (unsigned short*)(smem + TILE0);
    {
        const int g  = lane >> 2;
        const int tg = lane & 3;
        #pragma unroll
        for (int mt = 0; mt < 2; mt++)
            #pragma unroll
            for (int nt = 0; nt < 4; nt++) {
                const int r0  = wm * 32 + mt * 16 + g;
                const int col = wn * 32 + nt * 8 + tg * 2;
                *(unsigned*)(buf + r0 * TP2 + col) =
                    pack_f16x2(acc[mt][nt][0], acc[mt][nt][1]);
                *(unsigned*)(buf + (r0 + 8) * TP2 + col) =
                    pack_f16x2(acc[mt][nt][2], acc[mt][nt][3]);
            }
    }
    __syncthreads();
    {
        const int col  = tid & 127;      // local col 0..127
        const int half = tid >> 7;       // row half: 0..31 / 32..63
        uint32_t pk[16];
        #pragma unroll
        for (int q = 0; q < 16; q++) {
            unsigned lo = buf[(half * 32 + 2 * q) * TP2 + col];
            unsigned hi = buf[(half * 32 + 2 * q + 1) * TP2 + col];
            pk[q] = lo | (hi << 16);
        }
        unsigned short* dst = g_hWT + (size_t)(c0 + col) * NN + i0 + half * 32;
        #pragma unroll
        for (int q = 0; q < 4; q++)
            *(uint4*)(dst + q * 8) =
                make_uint4(pk[4 * q], pk[4 * q + 1], pk[4 * q + 2], pk[4 * q + 3]);
    }
}

// ---------------------------------------------------------------------------
// k_gat_mma: EXACT R13 kernel (untouched). M=64 x N=256, 256 thr, 2 CTA/SM,
// grid (128, 2), MUFU exp in gen_A, single sync per chunk.
// ---------------------------------------------------------------------------
__global__ __launch_bounds__(256, 2) void k_gat_mma(const int* __restrict__ adj)
{
    extern __shared__ __align__(1024) char smem[];
    const uint32_t sb = smem_u32(smem);

    const int tid  = threadIdx.x;
    const int lane = tid & 31;
    const int wid  = tid >> 5;
    const int wm   = wid & 1;      // warp row  (32 rows)
    const int wn   = wid >> 1;     // warp col  (64 cols)
    const int i0   = blockIdx.x * 64;
    const int ks   = blockIdx.y;
    const int k0s  = ks * KSL;

    int AHI[2], BHI[2];
    #pragma unroll
    for (int s = 0; s < 2; s++) {
        AHI[s] = TILE0 + s * STAGE_BYTES;
        BHI[s] = AHI[s] + 8192;
    }

    // ---- w-gen mapping: row iw, 16 k's starting at kb ----
    const int iw = tid >> 2;             // 0..63
    const int kb = (tid & 3) * 16;
    const float f1v  = g_f1[i0 + iw];
    const float smax = f1v + ord2f(g_fmax_u);
    const float Mrow = fmaxf(smax, 0.2f * smax);   // leaky(f1+Fmax) >= all e
    float zacc = 0.f;

    // ---- B cp.async mapping: n-row = tid, 8 chunks of 16B ----
    const int rB = tid;

    float acc[2][8][4];
    #pragma unroll
    for (int mt = 0; mt < 2; mt++)
        #pragma unroll
        for (int nt = 0; nt < 8; nt++)
            #pragma unroll
            for (int q = 0; q < 4; q++) acc[mt][nt][q] = 0.f;

    auto load_B = [&](int jt, int s) {
        const size_t gk = (size_t)rB * NN + k0s + jt * KT;
        #pragma unroll
        for (int cc = 0; cc < 8; cc++) {
            const uint32_t off = sw128((uint32_t)(rB * 128 + cc * 16));
            cp16(sb + BHI[s] + off, g_hWT + gk + cc * 8);
        }
    };

    auto gen_A = [&](int jt, int s) {
        const size_t kg = (size_t)k0s + jt * KT + kb;
        const int4*   ap = (const int4*)  (adj  + (size_t)(i0 + iw) * NN + kg);
        const float4* fp = (const float4*)(g_f2 + kg);
        int4   A0 = ap[0], A1 = ap[1], A2 = ap[2], A3 = ap[3];
        float4 F0 = fp[0], F1 = fp[1], F2 = fp[2], F3 = fp[3];
        const int   av[16] = {A0.x,A0.y,A0.z,A0.w, A1.x,A1.y,A1.z,A1.w,
                              A2.x,A2.y,A2.z,A2.w, A3.x,A3.y,A3.z,A3.w};
        const float fv[16] = {F0.x,F0.y,F0.z,F0.w, F1.x,F1.y,F1.z,F1.w,
                              F2.x,F2.y,F2.z,F2.w, F3.x,F3.y,F3.z,F3.w};
        float w[16];
        #pragma unroll
        for (int q = 0; q < 16; q++) {
            float sv = f1v + fv[q];
            float e  = fmaxf(sv, 0.2f * sv);     // leaky
            float we = __expf(e - Mrow);         // in (0,1]
            w[q] = (av[q] > 0) ? we : 0.f;
            zacc += w[q];
        }
        uint4 H0, H1;
        H0.x = pack_f16x2(w[0],  w[1]);  H0.y = pack_f16x2(w[2],  w[3]);
        H0.z = pack_f16x2(w[4],  w[5]);  H0.w = pack_f16x2(w[6],  w[7]);
        H1.x = pack_f16x2(w[8],  w[9]);  H1.y = pack_f16x2(w[10], w[11]);
        H1.z = pack_f16x2(w[12], w[13]); H1.w = pack_f16x2(w[14], w[15]);
        const uint32_t o0 = sw128((uint32_t)(iw * 128 + kb * 2));
        const uint32_t o1 = sw128((uint32_t)(iw * 128 + kb * 2 + 16));
        *(uint4*)(smem + AHI[s] + o0) = H0;
        *(uint4*)(smem + AHI[s] + o1) = H1;
    };

    // ldmatrix lane address components
    const int aRow = lane & 15;                        // A: row within 16-tile
    const int aH   = lane >> 4;                        // A: k-half
    const int bRow = (lane & 7) | ((lane >> 4) << 3);  // B: n-row within 16
    const int bH   = (lane >> 3) & 1;                  // B: k-half

    // ---- prologue: fill stage 0 ----
    load_B(0, 0);
    cp_commit();
    gen_A(0, 0);
    cp_wait0();
    __syncthreads();

    #pragma unroll 1
    for (int jt = 0; jt < NCHUNK; ++jt) {
        const int s = jt & 1;
        if (jt + 1 < NCHUNK) {
            load_B(jt + 1, s ^ 1);
            cp_commit();
            gen_A(jt + 1, s ^ 1);
        }

        // ---- MMA on stage s ----
        #pragma unroll
        for (int kk = 0; kk < 4; kk++) {
            uint32_t ah[2][4];
            #pragma unroll
            for (int mt = 0; mt < 2; mt++)
                ldsm4(ah[mt], sb + AHI[s] + sw128((uint32_t)(
                    (wm * 32 + mt * 16 + aRow) * 128 + kk * 32 + aH * 16)));
            uint32_t bh[4][4];
            #pragma unroll
            for (int p = 0; p < 4; p++)
                ldsm4(bh[p], sb + BHI[s] + sw128((uint32_t)(
                    (wn * 64 + p * 16 + bRow) * 128 + kk * 32 + bH * 16)));
            #pragma unroll
            for (int mt = 0; mt < 2; mt++)
                #pragma unroll
                for (int p = 0; p < 4; p++) {
                    mma16816(acc[mt][2 * p],     ah[mt], bh[p][0], bh[p][1]);
                    mma16816(acc[mt][2 * p + 1], ah[mt], bh[p][2], bh[p][3]);
                }
        }

        if (jt + 1 < NCHUNK) cp_wait0();
        __syncthreads();
    }

    // ---- epilogue: partial numerators + partial Z ----
    {
        float* npb = g_np + (size_t)ks * NN * DOUT;
        const int g  = lane >> 2;
        const int tg = lane & 3;
        #pragma unroll
        for (int mt = 0; mt < 2; mt++)
            #pragma unroll
            for (int nt = 0; nt < 8; nt++) {
                const int r0  = i0 + wm * 32 + mt * 16 + g;
                const int col = wn * 64 + nt * 8 + tg * 2;
                *(float2*)(npb + (size_t)r0 * DOUT + col) =
                    make_float2(acc[mt][nt][0], acc[mt][nt][1]);
                *(float2*)(npb + (size_t)(r0 + 8) * DOUT + col) =
                    make_float2(acc[mt][nt][2], acc[mt][nt][3]);
            }
    }
    float* zb = (float*)(smem + ZOFF);
    zb[tid] = zacc;
    __syncthreads();
    if (tid < 64)
        g_zp[ks * NN + i0 + tid] =
            zb[4 * tid] + zb[4 * tid + 1] + zb[4 * tid + 2] + zb[4 * tid + 3];
}

// ---------------------------------------------------------------------------
// k_combine: sum partials, softmax-normalize, ELU
// ---------------------------------------------------------------------------
__global__ void k_combine(float* __restrict__ out)
{
    const int row = blockIdx.x;
    const int c = threadIdx.x * 4;
    const float inv = 1.f / (g_zp[row] + g_zp[NN + row]);
    float4 p0 = *(const float4*)&g_np[(size_t)row * DOUT + c];
    float4 p1 = *(const float4*)&g_np[(size_t)(NN + row) * DOUT + c];
    float v[4] = {(p0.x + p1.x) * inv, (p0.y + p1.y) * inv,
                  (p0.z + p1.z) * inv, (p0.w + p1.w) * inv};
    #pragma unroll
    for (int q = 0; q < 4; q++)
        v[q] = (v[q] > 0.f) ? v[q] : expm1f(v[q]);
    *(float4*)&out[(size_t)row * DOUT + c] = make_float4(v[0], v[1], v[2], v[3]);
}

// ---------------------------------------------------------------------------
extern "C" void kernel_launch(void* const* d_in, const int* in_sizes, int n_in,
                              void* d_out, int out_size)
{
    const float* h   = (const float*)d_in[0];   // [8192, 512]
    const int*   adj = (const int*)  d_in[1];   // [8192, 8192]
    const float* W   = (const float*)d_in[2];   // [512, 256]
    const float* a   = (const float*)d_in[3];   // [512, 1]
    float* out = (float*)d_out;                 // [8192, 256]

    cudaFuncSetAttribute(k_hwt, cudaFuncAttributeMaxDynamicSharedMemorySize,
                         SMEM_HWT);
    cudaFuncSetAttribute(k_gat_mma, cudaFuncAttributeMaxDynamicSharedMemorySize,
                         SMEM_TOTAL);

    k_conv_h<<<NN * DIN / (256 * 8), 256>>>(h);
    k_prep_w<<<64, 256>>>(W, a);
    k_f1f2h<<<NN / 8, dim3(32, 8)>>>(h);
    k_hwt<<<dim3(2, NN / 64), 256, SMEM_HWT>>>();
    k_gat_mma<<<dim3(NN / 64, KSLICES), 256, SMEM_TOTAL>>>(adj);
    k_combine<<<NN, 64>>>(out);
}